// round 15
// baseline (speedup 1.0000x reference)
#include <cuda_runtime.h>
#include <cuda_fp16.h>
#include <cstdint>

#define BATCH 512
#define NODES 128
#define NFEAT 256
#define KTOT  32768          // NODES*NFEAT
#define SPLITS 32
#define KSLICE 1024          // KTOT/SPLITS
#define SEC   (BATCH*NFEAT)  // 131072

// ---------------------------------------------------------------------------
// Scratch (__device__ globals; allocation is forbidden)
// ---------------------------------------------------------------------------
__device__ __half g_gwT_h[NFEAT * NFEAT];                    // [g][f]
__device__ __half g_x_h[(size_t)BATCH * NODES * NFEAT];      // [b][node][f]
__device__ __half g_adj_h[(size_t)BATCH * NODES * NODES];    // [b][n][m]
__device__ __half g_fcw_h[(size_t)NFEAT * KTOT];             // [o][k]
__device__ __half g_mid_h[(size_t)BATCH * NODES * NFEAT];    // [b][node][g]
__device__ float  g_partial[(size_t)SPLITS * BATCH * NFEAT];

// ---------------------------------------------------------------------------
#define SW128(o) ((o) ^ (((o) >> 3) & 0x70))

__device__ __forceinline__ uint32_t smem_u32(const void* p) {
    uint32_t a;
    asm("{ .reg .u64 t; cvta.to.shared.u64 t, %1; cvt.u32.u64 %0, t; }"
        : "=r"(a) : "l"(p));
    return a;
}
__device__ __forceinline__ uint32_t pack2h(__half a, __half b) {
    __half2 t = __halves2half2(a, b);
    return *reinterpret_cast<uint32_t*>(&t);
}

// ---------------------------------------------------------------------------
// cp.async (base PTX, sm_80+)
// ---------------------------------------------------------------------------
__device__ __forceinline__ void cpa16(uint32_t s, const void* g) {
    asm volatile("cp.async.cg.shared.global [%0], [%1], 16;" :: "r"(s), "l"(g));
}
#define CP_COMMIT()  asm volatile("cp.async.commit_group;" ::: "memory")
#define CP_WAIT1()   asm volatile("cp.async.wait_group 1;" ::: "memory")
#define CP_WAIT0()   asm volatile("cp.async.wait_group 0;" ::: "memory")

// ---------------------------------------------------------------------------
// warp-MMA primitives (base PTX)
// ---------------------------------------------------------------------------
__device__ __forceinline__ void ldsm_x4(uint32_t addr, uint32_t* r) {
    asm volatile("ldmatrix.sync.aligned.m8n8.x4.shared.b16 {%0,%1,%2,%3}, [%4];"
        : "=r"(r[0]), "=r"(r[1]), "=r"(r[2]), "=r"(r[3]) : "r"(addr));
}
__device__ __forceinline__ void mma_f16(float* c, const uint32_t* a, const uint32_t* b) {
    asm volatile(
        "mma.sync.aligned.m16n8k16.row.col.f32.f16.f16.f32 "
        "{%0,%1,%2,%3}, {%4,%5,%6,%7}, {%8,%9}, {%0,%1,%2,%3};"
        : "+f"(c[0]), "+f"(c[1]), "+f"(c[2]), "+f"(c[3])
        : "r"(a[0]), "r"(a[1]), "r"(a[2]), "r"(a[3]), "r"(b[0]), "r"(b[1]));
}
// A frags, m64: 4 x ldsm_x4
__device__ __forceinline__ void load_afrags(uint32_t tbase, int m0w, int kb,
                                            int lane, uint32_t* a) {
    const int kpart = ((lane >> 4) << 4);
    #pragma unroll
    for (int i = 0; i < 4; i++) {
        int row = m0w + 16 * i + (lane & 15);
        ldsm_x4(tbase + SW128(row * 128 + kb + kpart), a + 4 * i);
    }
}
// B frags, n32 (4 n8-tiles) in 2 ldsm_x4; tile j at b + 4*(j>>1) + 2*(j&1)
__device__ __forceinline__ void load_b32(uint32_t tbase, int n0, int kb,
                                         int lane, uint32_t* b) {
    const int kpart = (((lane >> 3) & 1) << 4);
    const int tofs  = ((lane >> 4) & 1) * 8;
    int row = n0 + tofs + (lane & 7);
    ldsm_x4(tbase + SW128(row * 128 + kb + kpart),        b);
    ldsm_x4(tbase + SW128((row + 16) * 128 + kb + kpart), b + 4);
}
#define BJ(b, j) ((b) + 4 * ((j) >> 1) + 2 * ((j) & 1))

// 64x64 warp compute step: acc[128] += A(m64,k16) * B(n64,k16)^T
__device__ __forceinline__ void wmma64x64(float* acc, uint32_t abase, int m0,
                                          uint32_t bbase, int n0, int kb, int lane) {
    uint32_t ah[16], b1[8], b2[8];
    load_afrags(abase, m0, kb, lane, ah);
    load_b32(bbase, n0,      kb, lane, b1);
    load_b32(bbase, n0 + 32, kb, lane, b2);
    #pragma unroll
    for (int i = 0; i < 4; i++) {
        #pragma unroll
        for (int j = 0; j < 4; j++)
            mma_f16(acc + (i * 8 + j) * 4,     ah + 4 * i, BJ(b1, j));
        #pragma unroll
        for (int j = 0; j < 4; j++)
            mma_f16(acc + (i * 8 + 4 + j) * 4, ah + 4 * i, BJ(b2, j));
    }
}

// ---------------------------------------------------------------------------
// FUSED gemm1+gemm2: per batch job, supT never leaves SMEM.
//  phase1: supT[256g x 128n] = gwT @ x_b^T   (gwT resident in smem)
//  phase2: mid[128n x 256g] = adj_b @ supT + gcn_b
// SMEM: SUP 2x32KB | GW 4x32KB (resident) | RING 2x16KB (x / adj tiles)
// 256 threads, occupancy 1 (smem-bound), persistent over 512 jobs.
// ---------------------------------------------------------------------------
#define F_SUP  0
#define F_GW   65536
#define F_RING 196608
#define F_SMEM (229376 + 1024)

__global__ void __launch_bounds__(256, 1)
fused12(const __half* __restrict__ gwT, const __half* __restrict__ xh,
        const __half* __restrict__ adjh, const float* __restrict__ bias,
        __half* __restrict__ midh, int njobs)
{
    extern __shared__ char smraw[];
    char* sm = (char*)(((uintptr_t)smraw + 1023) & ~(uintptr_t)1023);
    const uint32_t sb = smem_u32(sm);

    const int tid  = threadIdx.x;
    const int lane = tid & 31;
    const int w    = tid >> 5;

    const int bid = blockIdx.x, jstep = gridDim.x;
    const int nj = (njobs - bid + jstep - 1) / jstep;
    if (nj <= 0) return;

    // ---- load gwT resident: 4 k-panels of [256 rows][128B], SW128 ----
    {
        #pragma unroll
        for (int it = 0; it < 32; it++) {
            int idx = tid + it * 256;          // 0..8191
            int p = idx >> 11;                 // panel
            int r = (idx >> 3) & 255;
            int c = idx & 7;
            cpa16(sb + F_GW + p * 32768 + SW128(r * 128 + c * 16),
                  gwT + (long)r * 256 + p * 64 + c * 8);
        }
        CP_COMMIT(); CP_WAIT0(); __syncthreads();
    }

    auto stage_x = [&](int q, int kt, int slot) {
        const __half* B = xh + (long)(bid + q * jstep) * (NODES * NFEAT);
        const uint32_t base = sb + F_RING + slot * 16384;
        const int k0 = kt * 64;
        #pragma unroll
        for (int it = 0; it < 4; it++) {
            int idx = tid + it * 256;
            int r = idx >> 3, c = idx & 7;
            cpa16(base + SW128(r * 128 + c * 16), B + (long)r * NFEAT + k0 + c * 8);
        }
    };
    auto stage_adj = [&](int q, int kt, int slot) {
        const __half* A = adjh + (long)(bid + q * jstep) * (NODES * NODES);
        const uint32_t base = sb + F_RING + slot * 16384;
        const int k0 = kt * 64;
        #pragma unroll
        for (int it = 0; it < 4; it++) {
            int idx = tid + it * 256;
            int r = idx >> 3, c = idx & 7;
            cpa16(base + SW128(r * 128 + c * 16), A + (long)r * NODES + k0 + c * 8);
        }
    };

    float acc[128];

    stage_x(0, 0, 0); CP_COMMIT();   // prologue

    for (int q = 0; q < nj; q++) {
        const bool lastj = (q == nj - 1);
        #pragma unroll
        for (int i = 0; i < 128; i++) acc[i] = 0.f;

        // ---- phase 1: CTA tile 256(g) x 128(node), warps 4x2 ----
        const int m1 = (w >> 1) * 64;   // g
        const int n1 = (w & 1) * 64;    // node
        #pragma unroll
        for (int kt = 0; kt < 4; kt++) {
            CP_WAIT0(); __syncthreads();
            if (kt < 3) { stage_x(q, kt + 1, (kt + 1) & 1); CP_COMMIT(); }
            else        { stage_adj(q, 0, 0);               CP_COMMIT(); }
            const uint32_t gp = sb + F_GW + kt * 32768;
            const uint32_t xs = sb + F_RING + (kt & 1) * 16384;
            #pragma unroll
            for (int ks = 0; ks < 4; ks++)
                wmma64x64(acc, gp, m1, xs, n1, ks * 32, lane);
        }

        // ---- supT epilogue: fp16 convert + STS into SUP panels ----
        #pragma unroll
        for (int i = 0; i < 4; i++) {
            #pragma unroll
            for (int j = 0; j < 8; j++) {
                float* c = acc + (i * 8 + j) * 4;
                int g0 = m1 + 16 * i + (lane >> 2);
                int nd = n1 + 8 * j + 2 * (lane & 3);
                int panel = nd >> 6;
                uint32_t bo0 = (uint32_t)g0 * 128 + (nd & 63) * 2;
                uint32_t bo1 = (uint32_t)(g0 + 8) * 128 + (nd & 63) * 2;
                *(uint32_t*)(sm + F_SUP + panel * 32768 + SW128(bo0)) =
                    pack2h(__float2half_rn(c[0]), __float2half_rn(c[1]));
                *(uint32_t*)(sm + F_SUP + panel * 32768 + SW128(bo1)) =
                    pack2h(__float2half_rn(c[2]), __float2half_rn(c[3]));
            }
        }
        #pragma unroll
        for (int i = 0; i < 128; i++) acc[i] = 0.f;

        // ---- phase 2: CTA tile 128(node) x 256(g), warps 2x4 ----
        const int m2 = (w >> 2) * 64;   // node
        const int n2 = (w & 3) * 64;    // g
        #pragma unroll
        for (int kt = 0; kt < 2; kt++) {
            CP_WAIT0(); __syncthreads();   // sync also publishes supT STS
            if (kt == 0)      { stage_adj(q, 1, 1);      CP_COMMIT(); }
            else if (!lastj)  { stage_x(q + 1, 0, 0);    CP_COMMIT(); }
            const uint32_t as = sb + F_RING + kt * 16384;
            const uint32_t sp = sb + F_SUP + kt * 32768;
            #pragma unroll
            for (int ks = 0; ks < 4; ks++)
                wmma64x64(acc, as, m2, sp, n2, ks * 32, lane);
        }

        // ---- mid epilogue: + gcn_b, fp16, global ----
        {
            __half* outH = midh + (long)(bid + q * jstep) * (NODES * NFEAT);
            #pragma unroll
            for (int i = 0; i < 4; i++) {
                #pragma unroll
                for (int j = 0; j < 8; j++) {
                    float* c = acc + (i * 8 + j) * 4;
                    int r0 = m2 + 16 * i + (lane >> 2);
                    int c0 = n2 + 8 * j + 2 * (lane & 3);
                    float b0 = __ldg(&bias[c0]), b1 = __ldg(&bias[c0 + 1]);
                    float v0 = c[0] + b0, v1 = c[1] + b1;
                    float v2 = c[2] + b0, v3 = c[3] + b1;
                    *(uint32_t*)&outH[(long)r0 * NFEAT + c0] =
                        pack2h(__float2half_rn(v0), __float2half_rn(v1));
                    *(uint32_t*)&outH[(long)(r0 + 8) * NFEAT + c0] =
                        pack2h(__float2half_rn(v2), __float2half_rn(v3));
                }
            }
        }
    }
}

// ---------------------------------------------------------------------------
// gemm3 (unchanged R14 shape): partial = mid @ fcw^T, warp 64x64, 128 thr
// ---------------------------------------------------------------------------
#define OFF_B  16384
#define STG    32768
#define NSTAGE 3
#define SMEM3  (NSTAGE * STG + 1024)
#define NTHR   128

__global__ void __launch_bounds__(NTHR, 2)
gemm3(const __half* __restrict__ Abase, const __half* __restrict__ Bbase,
      float* __restrict__ outFbase)
{
    extern __shared__ char smraw[];
    char* sm = (char*)(((uintptr_t)smraw + 1023) & ~(uintptr_t)1023);
    const uint32_t sb = smem_u32(sm);

    const int tid  = threadIdx.x;
    const int lane = tid & 31;
    const int w    = tid >> 5;
    const int m0w  = (w >> 1) * 64;
    const int n0w  = (w & 1) * 64;

    long split = blockIdx.x, mb = blockIdx.y, nh = blockIdx.z;
    const __half* A = Abase + (mb * 128) * (long)KTOT + split * KSLICE;
    const __half* B = Bbase + (nh * 128) * (long)KTOT + split * KSLICE;
    float* outF = outFbase + split * (long)SEC + (mb * 128) * (long)NFEAT + nh * 128;

    auto stage_load = [&](int t) {
        const uint32_t base = sb + (t % NSTAGE) * STG;
        const int k0 = t * 64;
        #pragma unroll
        for (int it = 0; it < 8; it++) {
            int idx = tid + it * NTHR;
            int row = idx >> 3, c = idx & 7;
            uint32_t so = SW128(row * 128 + c * 16);
            cpa16(base + so,         A + (long)row * KTOT + k0 + c * 8);
            cpa16(base + OFF_B + so, B + (long)row * KTOT + k0 + c * 8);
        }
    };

    float acc[128];
    #pragma unroll
    for (int i = 0; i < 128; i++) acc[i] = 0.f;

    const int T = KSLICE / 64;   // 16
    stage_load(0); CP_COMMIT();
    stage_load(1); CP_COMMIT();

    for (int t = 0; t < T; t++) {
        if (t + 1 < T) CP_WAIT1(); else CP_WAIT0();
        __syncthreads();
        if (t + 2 < T) { stage_load(t + 2); CP_COMMIT(); }
        const uint32_t base = sb + (t % NSTAGE) * STG;
        #pragma unroll
        for (int ks = 0; ks < 4; ks++)
            wmma64x64(acc, base, m0w, base + OFF_B, n0w, ks * 32, lane);
    }

    #pragma unroll
    for (int i = 0; i < 4; i++) {
        #pragma unroll
        for (int j = 0; j < 8; j++) {
            const float* c = acc + (i * 8 + j) * 4;
            int r0 = m0w + 16 * i + (lane >> 2);
            int c0 = n0w + 8 * j + 2 * (lane & 3);
            *(float2*)&outF[(long)r0 * NFEAT + c0]       = make_float2(c[0], c[1]);
            *(float2*)&outF[(long)(r0 + 8) * NFEAT + c0] = make_float2(c[2], c[3]);
        }
    }
}

// ---------------------------------------------------------------------------
// prep: fused fp32 -> fp16 conversion for three arrays in one launch
// ---------------------------------------------------------------------------
__global__ void __launch_bounds__(256)
conv3(const float* __restrict__ s0, __half* __restrict__ d0, long n0,
      const float* __restrict__ s1, __half* __restrict__ d1, long n1,
      const float* __restrict__ s2, __half* __restrict__ d2, long n2)
{
    long i = (long)blockIdx.x * 256 + threadIdx.x;
    const float* s; __half* d; long off;
    if (i < n0)            { s = s0; d = d0; off = i; }
    else if (i < n0 + n1)  { s = s1; d = d1; off = i - n0; }
    else if (i < n0 + n1 + n2) { s = s2; d = d2; off = i - n0 - n1; }
    else return;
    float4 v = ((const float4*)s)[off];
    ((uint2*)d)[off] = make_uint2(
        pack2h(__float2half_rn(v.x), __float2half_rn(v.y)),
        pack2h(__float2half_rn(v.z), __float2half_rn(v.w)));
}

// gcn_w transpose -> single fp16
__global__ void __launch_bounds__(256)
prep_wh(const float* __restrict__ wsrc, __half* __restrict__ dst)
{
    int g = blockIdx.x, f = threadIdx.x;
    dst[(long)g * NFEAT + f] = __float2half_rn(wsrc[(long)f * NFEAT + g]);
}

// ---------------------------------------------------------------------------
// finalize: reduce split-K partials + fc_b, write 3 output sections
// ---------------------------------------------------------------------------
__global__ void __launch_bounds__(256)
finalize(const float* __restrict__ P, const float* __restrict__ fc_b,
         const float* __restrict__ x, float* __restrict__ out)
{
    const int idx = blockIdx.x * blockDim.x + threadIdx.x;
    if (idx >= SEC) return;
    const int b = idx >> 8;
    const int f = idx & 255;
    float v = fc_b[f];
    #pragma unroll
    for (int s = 0; s < SPLITS; s++)
        v += P[(long)s * SEC + idx];
    out[idx]           = v;
    out[2 * SEC + idx] = v;
    out[SEC + idx]     = x[(long)b * KTOT + f];   // x[b,0,f]
}

// ---------------------------------------------------------------------------
extern "C" void kernel_launch(void* const* d_in, const int* in_sizes, int n_in,
                              void* d_out, int out_size)
{
    const float* x     = (const float*)d_in[0];
    const float* adj   = (const float*)d_in[1];
    const float* gcn_w = (const float*)d_in[2];
    const float* gcn_b = (const float*)d_in[3];
    const float* fc_w  = (const float*)d_in[4];
    const float* fc_b  = (const float*)d_in[5];
    float* out = (float*)d_out;

    __half *gwT_h, *x_h, *adj_h, *fcw_h, *mid_h;
    float* partial;
    cudaGetSymbolAddress((void**)&gwT_h,  g_gwT_h);
    cudaGetSymbolAddress((void**)&x_h,    g_x_h);
    cudaGetSymbolAddress((void**)&adj_h,  g_adj_h);
    cudaGetSymbolAddress((void**)&fcw_h,  g_fcw_h);
    cudaGetSymbolAddress((void**)&mid_h,  g_mid_h);
    cudaGetSymbolAddress((void**)&partial, g_partial);

    cudaFuncSetAttribute(fused12, cudaFuncAttributeMaxDynamicSharedMemorySize, F_SMEM);
    cudaFuncSetAttribute(gemm3,   cudaFuncAttributeMaxDynamicSharedMemorySize, SMEM3);

    int nsm = 148;
    cudaDeviceGetAttribute(&nsm, cudaDevAttrMultiProcessorCount, 0);

    // 0) preps
    prep_wh<<<NFEAT, NFEAT>>>(gcn_w, gwT_h);
    {
        long n0 = (long)BATCH * NODES * NFEAT / 4;    // x
        long n1 = (long)BATCH * NODES * NODES / 4;    // adj
        long n2 = (long)NFEAT * KTOT / 4;             // fc_w
        long tot = n0 + n1 + n2;
        conv3<<<(unsigned)((tot + 255) / 256), 256>>>(
            x, x_h, n0, adj, adj_h, n1, fc_w, fcw_h, n2);
    }

    // 1+2) fused: supT in SMEM, mid to global
    fused12<<<nsm, 256, F_SMEM>>>(gwT_h, x_h, adj_h, gcn_b, mid_h, BATCH);

    // 3) partial[s][m][n] = sum_{k in slice} mid[m][k]*fcw[n][k]  (single wave)
    {
        dim3 grid(SPLITS, BATCH / 128, 2);
        gemm3<<<grid, NTHR, SMEM3>>>(mid_h, fcw_h, partial);
    }
    // 4) reduce + bias + output sections
    finalize<<<SEC / 256, 256>>>(partial, fc_b, x, out);
}

// round 16
// speedup vs baseline: 1.3043x; 1.3043x over previous
#include <cuda_runtime.h>
#include <cuda_fp16.h>
#include <cstdint>

#define BATCH 512
#define NODES 128
#define NFEAT 256
#define KTOT  32768          // NODES*NFEAT
#define SPLITS 128
#define KSLICE 256           // KTOT/SPLITS
#define SEC   (BATCH*NFEAT)  // 131072

// ---------------------------------------------------------------------------
// Scratch (__device__ globals; allocation is forbidden)
// ---------------------------------------------------------------------------
__device__ __half g_gwT_h[NFEAT * NFEAT];                    // [g][f]
__device__ __half g_x_h[(size_t)BATCH * NODES * NFEAT];      // [b][node][f]
__device__ __half g_adj_h[(size_t)BATCH * NODES * NODES];    // [b][n][m]
__device__ __half g_fcw_h[(size_t)NFEAT * KTOT];             // [o][k]
__device__ __half g_supT_h[(size_t)BATCH * NFEAT * NODES];   // [b][g][node]
__device__ __half g_mid_h[(size_t)BATCH * NODES * NFEAT];    // [b][node][g]
__device__ float  g_partial[(size_t)SPLITS * BATCH * NFEAT];

// ---------------------------------------------------------------------------
#define SW128(o) ((o) ^ (((o) >> 3) & 0x70))

__device__ __forceinline__ uint32_t smem_u32(const void* p) {
    uint32_t a;
    asm("{ .reg .u64 t; cvta.to.shared.u64 t, %1; cvt.u32.u64 %0, t; }"
        : "=r"(a) : "l"(p));
    return a;
}
__device__ __forceinline__ uint32_t pack2h(__half a, __half b) {
    __half2 t = __halves2half2(a, b);
    return *reinterpret_cast<uint32_t*>(&t);
}

// ---------------------------------------------------------------------------
// cp.async (base PTX, sm_80+)
// ---------------------------------------------------------------------------
__device__ __forceinline__ void cpa16(uint32_t s, const void* g) {
    asm volatile("cp.async.cg.shared.global [%0], [%1], 16;" :: "r"(s), "l"(g));
}
#define CP_COMMIT()  asm volatile("cp.async.commit_group;" ::: "memory")
#define CP_WAIT1()   asm volatile("cp.async.wait_group 1;" ::: "memory")
#define CP_WAIT0()   asm volatile("cp.async.wait_group 0;" ::: "memory")

// ---------------------------------------------------------------------------
// warp-MMA primitives (base PTX)
// ---------------------------------------------------------------------------
__device__ __forceinline__ void ldsm_x4(uint32_t addr, uint32_t* r) {
    asm volatile("ldmatrix.sync.aligned.m8n8.x4.shared.b16 {%0,%1,%2,%3}, [%4];"
        : "=r"(r[0]), "=r"(r[1]), "=r"(r[2]), "=r"(r[3]) : "r"(addr));
}
__device__ __forceinline__ void mma_f16(float* c, const uint32_t* a, const uint32_t* b) {
    asm volatile(
        "mma.sync.aligned.m16n8k16.row.col.f32.f16.f16.f32 "
        "{%0,%1,%2,%3}, {%4,%5,%6,%7}, {%8,%9}, {%0,%1,%2,%3};"
        : "+f"(c[0]), "+f"(c[1]), "+f"(c[2]), "+f"(c[3])
        : "r"(a[0]), "r"(a[1]), "r"(a[2]), "r"(a[3]), "r"(b[0]), "r"(b[1]));
}
// A frags, m64: 4 x ldsm_x4
__device__ __forceinline__ void load_afrags(uint32_t tbase, int m0w, int kb,
                                            int lane, uint32_t* a) {
    const int kpart = ((lane >> 4) << 4);
    #pragma unroll
    for (int i = 0; i < 4; i++) {
        int row = m0w + 16 * i + (lane & 15);
        ldsm_x4(tbase + SW128(row * 128 + kb + kpart), a + 4 * i);
    }
}
// B frags, n32 (4 n8-tiles) in 2 ldsm_x4; tile j at b + 4*(j>>1) + 2*(j&1)
__device__ __forceinline__ void load_b32(uint32_t tbase, int n0, int kb,
                                         int lane, uint32_t* b) {
    const int kpart = (((lane >> 3) & 1) << 4);
    const int tofs  = ((lane >> 4) & 1) * 8;
    int row = n0 + tofs + (lane & 7);
    ldsm_x4(tbase + SW128(row * 128 + kb + kpart),        b);
    ldsm_x4(tbase + SW128((row + 16) * 128 + kb + kpart), b + 4);
}
#define BJ(b, j) ((b) + 4 * ((j) >> 1) + 2 * ((j) & 1))

// ---------------------------------------------------------------------------
// Single-fp16 GEMM, cross-job pipelined, warp tile 64x64, 128 threads, occ 2.
//  MODE 1 (NKT=4): A=gwT, B=x_b     -> supT fp16        [persistent]
//  MODE 2 (NKT=2): A=adj_b, B=supT  -> mid fp16 + bias  [persistent]
//  MODE 3 (NKT=4): A=mid, B=fcw     -> partial fp32     [persistent, SPLITS=128]
// ---------------------------------------------------------------------------
#define OFF_B  16384
#define STG    32768
#define NSTAGE 3
#define SMEM3  (NSTAGE * STG + 1024)   // 99328 B/CTA; 2 CTA/SM = 198656
#define NTHR   128

template <int MODE, int NKT>
__global__ void __launch_bounds__(NTHR, 2)
gemm_s(const __half* __restrict__ Abase, const __half* __restrict__ Bbase,
       long sA, long sB,
       const float* __restrict__ biasBase,
       float* __restrict__ outFbase, __half* __restrict__ outHbase,
       int njobs)
{
    extern __shared__ char smraw[];
    char* sm = (char*)(((uintptr_t)smraw + 1023) & ~(uintptr_t)1023);
    const uint32_t sb = smem_u32(sm);

    const int tid  = threadIdx.x;
    const int lane = tid & 31;
    const int w    = tid >> 5;          // 0..3
    const int m0w  = (w >> 1) * 64;
    const int n0w  = (w & 1) * 64;

    const int job0 = blockIdx.x, jstep = gridDim.x;
    const int nj = (njobs - job0 + jstep - 1) / jstep;
    if (nj <= 0) return;
    const int T = nj * NKT;   // total k-tiles this CTA streams

    auto jobAB = [&](int q, const __half*& A, const __half*& B) {
        const int job = job0 + q * jstep;
        if constexpr (MODE == 1) {
            A = Abase + (long)(job & 1) * 128 * NFEAT;            // gwT half
            B = Bbase + (long)(job >> 1) * (NODES * NFEAT);       // x_b
        } else if constexpr (MODE == 2) {
            A = Abase + (long)(job >> 1) * (NODES * NODES);       // adj_b
            B = Bbase + (long)(job >> 1) * (NFEAT * NODES)
                      + (long)(job & 1) * 128 * NODES;            // supT half
        } else {
            const int split = job >> 3, mb = (job >> 1) & 3, nh = job & 1;
            A = Abase + (long)(mb * 128) * KTOT + (long)split * KSLICE;   // mid
            B = Bbase + (long)(nh * 128) * KTOT + (long)split * KSLICE;   // fcw
        }
    };

    // stage global tile t into ring slot t%3 (128 threads x 8 iters x 2 arrays)
    auto stage_load = [&](int t) {
        const int q  = t / NKT;
        const int kt = t % NKT;
        const __half *A, *B;
        jobAB(q, A, B);
        const uint32_t base = sb + (t % NSTAGE) * STG;
        const int k0 = kt * 64;
        #pragma unroll
        for (int it = 0; it < 8; it++) {
            int idx = tid + it * NTHR;
            int row = idx >> 3, c = idx & 7;
            uint32_t so = SW128(row * 128 + c * 16);
            cpa16(base + so,         A + (long)row * sA + k0 + c * 8);
            cpa16(base + OFF_B + so, B + (long)row * sB + k0 + c * 8);
        }
    };

    float acc[128];
    #pragma unroll
    for (int i = 0; i < 128; i++) acc[i] = 0.f;

    stage_load(0); CP_COMMIT();
    if (T > 1) { stage_load(1); CP_COMMIT(); }

    for (int t = 0; t < T; t++) {
        if (t + 1 < T) CP_WAIT1(); else CP_WAIT0();
        __syncthreads();
        if (t + 2 < T) { stage_load(t + 2); CP_COMMIT(); }

        const uint32_t base = sb + (t % NSTAGE) * STG;
        #pragma unroll
        for (int ks = 0; ks < 4; ks++) {
            const int kb = ks * 32;
            uint32_t ah[16], b1[8], b2[8];
            load_afrags(base,      m0w, kb, lane, ah);
            load_b32(base + OFF_B, n0w,      kb, lane, b1);
            load_b32(base + OFF_B, n0w + 32, kb, lane, b2);
            #pragma unroll
            for (int i = 0; i < 4; i++) {
                #pragma unroll
                for (int j = 0; j < 4; j++)
                    mma_f16(acc + (i * 8 + j) * 4,       ah + 4 * i, BJ(b1, j));
                #pragma unroll
                for (int j = 0; j < 4; j++)
                    mma_f16(acc + (i * 8 + 4 + j) * 4,   ah + 4 * i, BJ(b2, j));
            }
        }

        if (t % NKT == NKT - 1) {
            // ---- job epilogue (register-only; next loads already in flight) ----
            const int job = job0 + (t / NKT) * jstep;
            int ldc, coloff = 0;
            long outOfs = 0;
            const float* bias = biasBase;
            float* outF = outFbase;
            __half* outH = outHbase;
            if constexpr (MODE == 1) {
                long b = job >> 1, mh = job & 1;
                outOfs = b * (long)(NFEAT * NODES) + mh * 128 * NODES;
                ldc = NODES;
            } else if constexpr (MODE == 2) {
                long b = job >> 1, nh = job & 1;
                outOfs = b * (long)(NODES * NFEAT);
                bias += nh * 128;
                ldc = NFEAT; coloff = (int)nh * 128;
            } else {
                const int split = job >> 3, mb = (job >> 1) & 3, nh = job & 1;
                outF += (long)split * SEC + (long)(mb * 128) * NFEAT + nh * 128;
                ldc = NFEAT;
            }
            #pragma unroll
            for (int i = 0; i < 4; i++) {
                #pragma unroll
                for (int j = 0; j < 8; j++) {
                    float* c = acc + (i * 8 + j) * 4;
                    int r0 = m0w + 16 * i + (lane >> 2);
                    int c0 = n0w + 8 * j + 2 * (lane & 3);
                    if constexpr (MODE == 3) {
                        *(float2*)&outF[(long)r0 * ldc + c0]       = make_float2(c[0], c[1]);
                        *(float2*)&outF[(long)(r0 + 8) * ldc + c0] = make_float2(c[2], c[3]);
                    } else {
                        float v0 = c[0], v1 = c[1], v2 = c[2], v3 = c[3];
                        if constexpr (MODE == 2) {
                            float b0 = __ldg(&bias[c0]), b1 = __ldg(&bias[c0 + 1]);
                            v0 += b0; v1 += b1; v2 += b0; v3 += b1;
                        }
                        long o0 = outOfs + (long)r0 * ldc + coloff + c0;
                        long o1 = outOfs + (long)(r0 + 8) * ldc + coloff + c0;
                        *(uint32_t*)&outH[o0] = pack2h(__float2half_rn(v0), __float2half_rn(v1));
                        *(uint32_t*)&outH[o1] = pack2h(__float2half_rn(v2), __float2half_rn(v3));
                    }
                    c[0] = 0.f; c[1] = 0.f; c[2] = 0.f; c[3] = 0.f;
                }
            }
        }
    }
}

// ---------------------------------------------------------------------------
// prep: fused fp32 -> fp16 conversion, grid-stride with MLP=4
// ---------------------------------------------------------------------------
__device__ __forceinline__ void conv_body(
    long i, const float* __restrict__ s0, __half* __restrict__ d0, long n0,
    const float* __restrict__ s1, __half* __restrict__ d1, long n1,
    const float* __restrict__ s2, __half* __restrict__ d2)
{
    const float* s; __half* d; long off;
    if (i < n0)           { s = s0; d = d0; off = i; }
    else if (i < n0 + n1) { s = s1; d = d1; off = i - n0; }
    else                  { s = s2; d = d2; off = i - n0 - n1; }
    float4 v = ((const float4*)s)[off];
    ((uint2*)d)[off] = make_uint2(
        pack2h(__float2half_rn(v.x), __float2half_rn(v.y)),
        pack2h(__float2half_rn(v.z), __float2half_rn(v.w)));
}

__global__ void __launch_bounds__(256)
conv3(const float* __restrict__ s0, __half* __restrict__ d0, long n0,
      const float* __restrict__ s1, __half* __restrict__ d1, long n1,
      const float* __restrict__ s2, __half* __restrict__ d2, long n2)
{
    const long tot = n0 + n1 + n2;
    const long stride = (long)gridDim.x * 256;
    long i = (long)blockIdx.x * 256 + threadIdx.x;
    for (; i + 3 * stride < tot; i += 4 * stride) {
        conv_body(i,              s0, d0, n0, s1, d1, n1, s2, d2);
        conv_body(i + stride,     s0, d0, n0, s1, d1, n1, s2, d2);
        conv_body(i + 2 * stride, s0, d0, n0, s1, d1, n1, s2, d2);
        conv_body(i + 3 * stride, s0, d0, n0, s1, d1, n1, s2, d2);
    }
    for (; i < tot; i += stride)
        conv_body(i, s0, d0, n0, s1, d1, n1, s2, d2);
}

// gcn_w transpose -> single fp16
__global__ void __launch_bounds__(256)
prep_wh(const float* __restrict__ wsrc, __half* __restrict__ dst)
{
    int g = blockIdx.x, f = threadIdx.x;
    dst[(long)g * NFEAT + f] = __float2half_rn(wsrc[(long)f * NFEAT + g]);
}

// ---------------------------------------------------------------------------
// finalize: reduce split-K partials + fc_b, write 3 output sections
// ---------------------------------------------------------------------------
__global__ void __launch_bounds__(256)
finalize(const float* __restrict__ P, const float* __restrict__ fc_b,
         const float* __restrict__ x, float* __restrict__ out)
{
    const int idx = blockIdx.x * blockDim.x + threadIdx.x;
    if (idx >= SEC) return;
    const int b = idx >> 8;
    const int f = idx & 255;
    float v = fc_b[f];
    #pragma unroll 16
    for (int s = 0; s < SPLITS; s++)
        v += P[(long)s * SEC + idx];
    out[idx]           = v;
    out[2 * SEC + idx] = v;
    out[SEC + idx]     = x[(long)b * KTOT + f];   // x[b,0,f]
}

// ---------------------------------------------------------------------------
extern "C" void kernel_launch(void* const* d_in, const int* in_sizes, int n_in,
                              void* d_out, int out_size)
{
    const float* x     = (const float*)d_in[0];
    const float* adj   = (const float*)d_in[1];
    const float* gcn_w = (const float*)d_in[2];
    const float* gcn_b = (const float*)d_in[3];
    const float* fc_w  = (const float*)d_in[4];
    const float* fc_b  = (const float*)d_in[5];
    float* out = (float*)d_out;

    __half *gwT_h, *x_h, *adj_h, *fcw_h, *supT_h, *mid_h;
    float* partial;
    cudaGetSymbolAddress((void**)&gwT_h,  g_gwT_h);
    cudaGetSymbolAddress((void**)&x_h,    g_x_h);
    cudaGetSymbolAddress((void**)&adj_h,  g_adj_h);
    cudaGetSymbolAddress((void**)&fcw_h,  g_fcw_h);
    cudaGetSymbolAddress((void**)&supT_h, g_supT_h);
    cudaGetSymbolAddress((void**)&mid_h,  g_mid_h);
    cudaGetSymbolAddress((void**)&partial, g_partial);

    cudaFuncSetAttribute((const void*)gemm_s<1,4>, cudaFuncAttributeMaxDynamicSharedMemorySize, SMEM3);
    cudaFuncSetAttribute((const void*)gemm_s<2,2>, cudaFuncAttributeMaxDynamicSharedMemorySize, SMEM3);
    cudaFuncSetAttribute((const void*)gemm_s<3,4>, cudaFuncAttributeMaxDynamicSharedMemorySize, SMEM3);

    int nsm = 148;
    cudaDeviceGetAttribute(&nsm, cudaDevAttrMultiProcessorCount, 0);
    const int pgrid = 2 * nsm;    // occ-2 persistent grid

    // 0) preps
    prep_wh<<<NFEAT, NFEAT>>>(gcn_w, gwT_h);
    {
        long n0 = (long)BATCH * NODES * NFEAT / 4;    // x
        long n1 = (long)BATCH * NODES * NODES / 4;    // adj
        long n2 = (long)NFEAT * KTOT / 4;             // fc_w
        conv3<<<2048, 256>>>(x, x_h, n0, adj, adj_h, n1, fc_w, fcw_h, n2);
    }

    // 1) supT[b][g][node] = sum_f gwT[g][f] * x_b[node][f]   (persistent)
    gemm_s<1,4><<<pgrid, NTHR, SMEM3>>>(
        gwT_h, x_h, NFEAT, NFEAT, nullptr, nullptr, supT_h, BATCH * 2);

    // 2) mid[b][node][g] = sum_k adj_b[node][k]*supT_b[g][k] + gcn_b[g]  (persistent)
    gemm_s<2,2><<<pgrid, NTHR, SMEM3>>>(
        adj_h, supT_h, NODES, NODES, gcn_b, nullptr, mid_h, BATCH * 2);

    // 3) partial[s][m][n] = sum_{k in slice} mid[m][k]*fcw[n][k]  (persistent, fine split)
    gemm_s<3,4><<<pgrid, NTHR, SMEM3>>>(
        mid_h, fcw_h, KTOT, KTOT, nullptr, partial, nullptr, SPLITS * 8);

    // 4) reduce + bias + output sections
    finalize<<<SEC / 256, 256>>>(partial, fc_b, x, out);
}

// round 17
// speedup vs baseline: 1.4190x; 1.0879x over previous
#include <cuda_runtime.h>
#include <cuda_fp16.h>
#include <cstdint>

#define BATCH 512
#define NODES 128
#define NFEAT 256
#define KTOT  32768          // NODES*NFEAT
#define SPLITS 32
#define KSLICE 1024          // KTOT/SPLITS
#define SEC   (BATCH*NFEAT)  // 131072

// ---------------------------------------------------------------------------
// Scratch (__device__ globals; allocation is forbidden)
// ---------------------------------------------------------------------------
__device__ __half g_gwT_h[NFEAT * NFEAT];                    // [g][f]
__device__ __half g_x_h[(size_t)BATCH * NODES * NFEAT];      // [b][node][f]
__device__ __half g_adj_h[(size_t)BATCH * NODES * NODES];    // [b][n][m]
__device__ __half g_fcw_h[(size_t)NFEAT * KTOT];             // [o][k]
__device__ __half g_supT_h[(size_t)BATCH * NFEAT * NODES];   // [b][g][node]
__device__ __half g_mid_h[(size_t)BATCH * NODES * NFEAT];    // [b][node][g]
__device__ float  g_partial[(size_t)SPLITS * BATCH * NFEAT];

// ---------------------------------------------------------------------------
#define SW128(o) ((o) ^ (((o) >> 3) & 0x70))

__device__ __forceinline__ uint32_t smem_u32(const void* p) {
    uint32_t a;
    asm("{ .reg .u64 t; cvta.to.shared.u64 t, %1; cvt.u32.u64 %0, t; }"
        : "=r"(a) : "l"(p));
    return a;
}
__device__ __forceinline__ uint32_t pack2h(__half a, __half b) {
    __half2 t = __halves2half2(a, b);
    return *reinterpret_cast<uint32_t*>(&t);
}

// ---------------------------------------------------------------------------
// cp.async (base PTX, sm_80+)
// ---------------------------------------------------------------------------
__device__ __forceinline__ void cpa16(uint32_t s, const void* g) {
    asm volatile("cp.async.cg.shared.global [%0], [%1], 16;" :: "r"(s), "l"(g));
}
#define CP_COMMIT()  asm volatile("cp.async.commit_group;" ::: "memory")
#define CP_WAIT1()   asm volatile("cp.async.wait_group 1;" ::: "memory")
#define CP_WAIT0()   asm volatile("cp.async.wait_group 0;" ::: "memory")

// ---------------------------------------------------------------------------
// warp-MMA primitives (base PTX)
// ---------------------------------------------------------------------------
__device__ __forceinline__ void ldsm_x4(uint32_t addr, uint32_t* r) {
    asm volatile("ldmatrix.sync.aligned.m8n8.x4.shared.b16 {%0,%1,%2,%3}, [%4];"
        : "=r"(r[0]), "=r"(r[1]), "=r"(r[2]), "=r"(r[3]) : "r"(addr));
}
__device__ __forceinline__ void mma_f16(float* c, const uint32_t* a, const uint32_t* b) {
    asm volatile(
        "mma.sync.aligned.m16n8k16.row.col.f32.f16.f16.f32 "
        "{%0,%1,%2,%3}, {%4,%5,%6,%7}, {%8,%9}, {%0,%1,%2,%3};"
        : "+f"(c[0]), "+f"(c[1]), "+f"(c[2]), "+f"(c[3])
        : "r"(a[0]), "r"(a[1]), "r"(a[2]), "r"(a[3]), "r"(b[0]), "r"(b[1]));
}
// A frags, m64: 4 x ldsm_x4
__device__ __forceinline__ void load_afrags(uint32_t tbase, int m0w, int kb,
                                            int lane, uint32_t* a) {
    const int kpart = ((lane >> 4) << 4);
    #pragma unroll
    for (int i = 0; i < 4; i++) {
        int row = m0w + 16 * i + (lane & 15);
        ldsm_x4(tbase + SW128(row * 128 + kb + kpart), a + 4 * i);
    }
}
// B frags, n32 (4 n8-tiles) in 2 ldsm_x4; tile j at b + 4*(j>>1) + 2*(j&1)
__device__ __forceinline__ void load_b32(uint32_t tbase, int n0, int kb,
                                         int lane, uint32_t* b) {
    const int kpart = (((lane >> 3) & 1) << 4);
    const int tofs  = ((lane >> 4) & 1) * 8;
    int row = n0 + tofs + (lane & 7);
    ldsm_x4(tbase + SW128(row * 128 + kb + kpart),        b);
    ldsm_x4(tbase + SW128((row + 16) * 128 + kb + kpart), b + 4);
}
#define BJ(b, j) ((b) + 4 * ((j) >> 1) + 2 * ((j) & 1))

// 64x64 warp compute: acc[128] += A(m64,k16) * B(n64,k16)^T
__device__ __forceinline__ void wmma64x64(float* acc, uint32_t abase, int m0,
                                          uint32_t bbase, int n0, int kb, int lane) {
    uint32_t ah[16], b1[8], b2[8];
    load_afrags(abase, m0, kb, lane, ah);
    load_b32(bbase, n0,      kb, lane, b1);
    load_b32(bbase, n0 + 32, kb, lane, b2);
    #pragma unroll
    for (int i = 0; i < 4; i++) {
        #pragma unroll
        for (int j = 0; j < 4; j++)
            mma_f16(acc + (i * 8 + j) * 4,     ah + 4 * i, BJ(b1, j));
        #pragma unroll
        for (int j = 0; j < 4; j++)
            mma_f16(acc + (i * 8 + 4 + j) * 4, ah + 4 * i, BJ(b2, j));
    }
}

#define NTHR   128

// ---------------------------------------------------------------------------
// gemm1r: supT = gwT @ x^T with RESIDENT gwT half in SMEM.
// grid = 2*nsm; CTA (bid) owns gwT half mh = bid&1 (loaded ONCE), streams
// batches b = (bid>>1) + q*(grid/2). Ring stages only x (3 x 16KB).
// SMEM: GW 4x16KB resident | RING 3x16KB = 114688 (+pad); occ 2.
// Math order identical to staged MODE1 -> bit-identical output.
// ---------------------------------------------------------------------------
#define R1_GW   0
#define R1_RING 65536
#define R1_SMEM (65536 + 49152 + 1024)

__global__ void __launch_bounds__(NTHR, 2)
gemm1r(const __half* __restrict__ gwT, const __half* __restrict__ xh,
       __half* __restrict__ supT, int nbatch)
{
    extern __shared__ char smraw[];
    char* sm = (char*)(((uintptr_t)smraw + 1023) & ~(uintptr_t)1023);
    const uint32_t sb = smem_u32(sm);

    const int tid  = threadIdx.x;
    const int lane = tid & 31;
    const int w    = tid >> 5;
    const int m0w  = (w >> 1) * 64;
    const int n0w  = (w & 1) * 64;

    const int mh    = blockIdx.x & 1;
    const int c0    = blockIdx.x >> 1;
    const int cstep = gridDim.x >> 1;
    const int nj = (nbatch - c0 + cstep - 1) / cstep;
    if (nj <= 0) return;
    const int T = nj * 4;

    // ---- resident gwT half: 4 k-panels of [128 rows][128B] (group 0) ----
    {
        #pragma unroll
        for (int it = 0; it < 32; it++) {
            int idx = tid + it * NTHR;       // 0..4095 16B chunks
            int p = idx >> 10;               // panel
            int r = (idx >> 3) & 127;
            int c = idx & 7;
            cpa16(sb + R1_GW + p * 16384 + SW128(r * 128 + c * 16),
                  gwT + (long)(mh * 128 + r) * NFEAT + p * 64 + c * 8);
        }
        CP_COMMIT();
    }

    auto stage_x = [&](int t) {
        const int q = t >> 2, kt = t & 3;
        const __half* B = xh + (long)(c0 + q * cstep) * (NODES * NFEAT);
        const uint32_t base = sb + R1_RING + (t % 3) * 16384;
        const int k0 = kt * 64;
        #pragma unroll
        for (int it = 0; it < 8; it++) {
            int idx = tid + it * NTHR;       // 0..1023
            int r = idx >> 3, c = idx & 7;
            cpa16(base + SW128(r * 128 + c * 16),
                  B + (long)r * NFEAT + k0 + c * 8);
        }
    };

    float acc[128];
    #pragma unroll
    for (int i = 0; i < 128; i++) acc[i] = 0.f;

    stage_x(0); CP_COMMIT();
    if (T > 1) { stage_x(1); CP_COMMIT(); }

    for (int t = 0; t < T; t++) {
        if (t + 1 < T) CP_WAIT1(); else CP_WAIT0();   // also drains resident grp
        __syncthreads();
        if (t + 2 < T) { stage_x(t + 2); CP_COMMIT(); }

        const int kt = t & 3;
        const uint32_t gp = sb + R1_GW + kt * 16384;
        const uint32_t xs = sb + R1_RING + (t % 3) * 16384;
        #pragma unroll
        for (int ks = 0; ks < 4; ks++)
            wmma64x64(acc, gp, m0w, xs, n0w, ks * 32, lane);

        if (kt == 3) {
            const long b = c0 + (long)(t >> 2) * cstep;
            const long outOfs = b * (long)(NFEAT * NODES) + (long)mh * 128 * NODES;
            #pragma unroll
            for (int i = 0; i < 4; i++) {
                #pragma unroll
                for (int j = 0; j < 8; j++) {
                    float* c = acc + (i * 8 + j) * 4;
                    int r0 = m0w + 16 * i + (lane >> 2);
                    int cc = n0w + 8 * j + 2 * (lane & 3);
                    long o0 = outOfs + (long)r0 * NODES + cc;
                    long o1 = outOfs + (long)(r0 + 8) * NODES + cc;
                    *(uint32_t*)&supT[o0] = pack2h(__float2half_rn(c[0]), __float2half_rn(c[1]));
                    *(uint32_t*)&supT[o1] = pack2h(__float2half_rn(c[2]), __float2half_rn(c[3]));
                    c[0] = 0.f; c[1] = 0.f; c[2] = 0.f; c[3] = 0.f;
                }
            }
        }
    }
}

// ---------------------------------------------------------------------------
// gemm_s (R14): cross-job pipelined, warp tile 64x64, 128 threads, occ 2.
//  MODE 2 (NKT=2):  A=adj_b, B=supT  -> mid fp16 + bias  [persistent]
//  MODE 3 (NKT=16): A=mid, B=fcw     -> partial fp32     [1-wave grid]
// ---------------------------------------------------------------------------
#define OFF_B  16384
#define STG    32768
#define NSTAGE 3
#define SMEM3  (NSTAGE * STG + 1024)

template <int MODE, int NKT>
__global__ void __launch_bounds__(NTHR, 2)
gemm_s(const __half* __restrict__ Abase, const __half* __restrict__ Bbase,
       long sA, long sB,
       const float* __restrict__ biasBase,
       float* __restrict__ outFbase, __half* __restrict__ outHbase,
       int njobs)
{
    extern __shared__ char smraw[];
    char* sm = (char*)(((uintptr_t)smraw + 1023) & ~(uintptr_t)1023);
    const uint32_t sb = smem_u32(sm);

    const int tid  = threadIdx.x;
    const int lane = tid & 31;
    const int w    = tid >> 5;
    const int m0w  = (w >> 1) * 64;
    const int n0w  = (w & 1) * 64;

    int job0, jstep, nj;
    const __half *A3 = nullptr, *B3 = nullptr;
    if constexpr (MODE == 3) {
        job0 = 0; jstep = 1; nj = 1;
        long split = blockIdx.x, mb = blockIdx.y, nh = blockIdx.z;
        A3 = Abase + (mb * 128) * (long)KTOT + split * KSLICE;
        B3 = Bbase + (nh * 128) * (long)KTOT + split * KSLICE;
    } else {
        job0 = blockIdx.x; jstep = gridDim.x;
        nj = (njobs - job0 + jstep - 1) / jstep;
        if (nj <= 0) return;
    }
    const int T = nj * NKT;

    auto jobAB = [&](int q, const __half*& A, const __half*& B) {
        if constexpr (MODE == 2) {
            int job = job0 + q * jstep;
            A = Abase + (long)(job >> 1) * (NODES * NODES);
            B = Bbase + (long)(job >> 1) * (NFEAT * NODES)
                      + (long)(job & 1) * 128 * NODES;
        } else {
            A = A3; B = B3;
        }
    };

    auto stage_load = [&](int t) {
        const int q  = t / NKT;
        const int kt = t % NKT;
        const __half *A, *B;
        jobAB(q, A, B);
        const uint32_t base = sb + (t % NSTAGE) * STG;
        const int k0 = kt * 64;
        #pragma unroll
        for (int it = 0; it < 8; it++) {
            int idx = tid + it * NTHR;
            int row = idx >> 3, c = idx & 7;
            uint32_t so = SW128(row * 128 + c * 16);
            cpa16(base + so,         A + (long)row * sA + k0 + c * 8);
            cpa16(base + OFF_B + so, B + (long)row * sB + k0 + c * 8);
        }
    };

    float acc[128];
    #pragma unroll
    for (int i = 0; i < 128; i++) acc[i] = 0.f;

    stage_load(0); CP_COMMIT();
    if (T > 1) { stage_load(1); CP_COMMIT(); }

    for (int t = 0; t < T; t++) {
        if (t + 1 < T) CP_WAIT1(); else CP_WAIT0();
        __syncthreads();
        if (t + 2 < T) { stage_load(t + 2); CP_COMMIT(); }

        const uint32_t base = sb + (t % NSTAGE) * STG;
        #pragma unroll
        for (int ks = 0; ks < 4; ks++)
            wmma64x64(acc, base, m0w, base + OFF_B, n0w, ks * 32, lane);

        if (t % NKT == NKT - 1) {
            const int job = job0 + (t / NKT) * jstep;
            int ldc, coloff = 0;
            long outOfs = 0;
            const float* bias = biasBase;
            float* outF = outFbase;
            __half* outH = outHbase;
            if constexpr (MODE == 2) {
                long b = job >> 1, nh = job & 1;
                outOfs = b * (long)(NODES * NFEAT);
                bias += nh * 128;
                ldc = NFEAT; coloff = (int)nh * 128;
            } else {
                long split = blockIdx.x, mb = blockIdx.y, nh = blockIdx.z;
                outF += split * (long)SEC + (mb * 128) * (long)NFEAT + nh * 128;
                ldc = NFEAT;
            }
            #pragma unroll
            for (int i = 0; i < 4; i++) {
                #pragma unroll
                for (int j = 0; j < 8; j++) {
                    float* c = acc + (i * 8 + j) * 4;
                    int r0 = m0w + 16 * i + (lane >> 2);
                    int c0 = n0w + 8 * j + 2 * (lane & 3);
                    if constexpr (MODE == 3) {
                        *(float2*)&outF[(long)r0 * ldc + c0]       = make_float2(c[0], c[1]);
                        *(float2*)&outF[(long)(r0 + 8) * ldc + c0] = make_float2(c[2], c[3]);
                    } else {
                        float b0 = __ldg(&bias[c0]), b1 = __ldg(&bias[c0 + 1]);
                        float v0 = c[0] + b0, v1 = c[1] + b1;
                        float v2 = c[2] + b0, v3 = c[3] + b1;
                        long o0 = outOfs + (long)r0 * ldc + coloff + c0;
                        long o1 = outOfs + (long)(r0 + 8) * ldc + coloff + c0;
                        *(uint32_t*)&outH[o0] = pack2h(__float2half_rn(v0), __float2half_rn(v1));
                        *(uint32_t*)&outH[o1] = pack2h(__float2half_rn(v2), __float2half_rn(v3));
                    }
                    c[0] = 0.f; c[1] = 0.f; c[2] = 0.f; c[3] = 0.f;
                }
            }
        }
    }
}

// ---------------------------------------------------------------------------
// prep: fused fp32 -> fp16 conversion, grid-stride MLP=4
// ---------------------------------------------------------------------------
__device__ __forceinline__ void conv_body(
    long i, const float* __restrict__ s0, __half* __restrict__ d0, long n0,
    const float* __restrict__ s1, __half* __restrict__ d1, long n1,
    const float* __restrict__ s2, __half* __restrict__ d2)
{
    const float* s; __half* d; long off;
    if (i < n0)           { s = s0; d = d0; off = i; }
    else if (i < n0 + n1) { s = s1; d = d1; off = i - n0; }
    else                  { s = s2; d = d2; off = i - n0 - n1; }
    float4 v = ((const float4*)s)[off];
    ((uint2*)d)[off] = make_uint2(
        pack2h(__float2half_rn(v.x), __float2half_rn(v.y)),
        pack2h(__float2half_rn(v.z), __float2half_rn(v.w)));
}

__global__ void __launch_bounds__(256)
conv3(const float* __restrict__ s0, __half* __restrict__ d0, long n0,
      const float* __restrict__ s1, __half* __restrict__ d1, long n1,
      const float* __restrict__ s2, __half* __restrict__ d2, long n2)
{
    const long tot = n0 + n1 + n2;
    const long stride = (long)gridDim.x * 256;
    long i = (long)blockIdx.x * 256 + threadIdx.x;
    for (; i + 3 * stride < tot; i += 4 * stride) {
        conv_body(i,              s0, d0, n0, s1, d1, n1, s2, d2);
        conv_body(i + stride,     s0, d0, n0, s1, d1, n1, s2, d2);
        conv_body(i + 2 * stride, s0, d0, n0, s1, d1, n1, s2, d2);
        conv_body(i + 3 * stride, s0, d0, n0, s1, d1, n1, s2, d2);
    }
    for (; i < tot; i += stride)
        conv_body(i, s0, d0, n0, s1, d1, n1, s2, d2);
}

// gcn_w transpose -> single fp16
__global__ void __launch_bounds__(256)
prep_wh(const float* __restrict__ wsrc, __half* __restrict__ dst)
{
    int g = blockIdx.x, f = threadIdx.x;
    dst[(long)g * NFEAT + f] = __float2half_rn(wsrc[(long)f * NFEAT + g]);
}

// ---------------------------------------------------------------------------
// finalize: reduce split-K partials + fc_b, write 3 output sections
// ---------------------------------------------------------------------------
__global__ void __launch_bounds__(256)
finalize(const float* __restrict__ P, const float* __restrict__ fc_b,
         const float* __restrict__ x, float* __restrict__ out)
{
    const int idx = blockIdx.x * blockDim.x + threadIdx.x;
    if (idx >= SEC) return;
    const int b = idx >> 8;
    const int f = idx & 255;
    float v = fc_b[f];
    #pragma unroll
    for (int s = 0; s < SPLITS; s++)
        v += P[(long)s * SEC + idx];
    out[idx]           = v;
    out[2 * SEC + idx] = v;
    out[SEC + idx]     = x[(long)b * KTOT + f];   // x[b,0,f]
}

// ---------------------------------------------------------------------------
extern "C" void kernel_launch(void* const* d_in, const int* in_sizes, int n_in,
                              void* d_out, int out_size)
{
    const float* x     = (const float*)d_in[0];
    const float* adj   = (const float*)d_in[1];
    const float* gcn_w = (const float*)d_in[2];
    const float* gcn_b = (const float*)d_in[3];
    const float* fc_w  = (const float*)d_in[4];
    const float* fc_b  = (const float*)d_in[5];
    float* out = (float*)d_out;

    __half *gwT_h, *x_h, *adj_h, *fcw_h, *supT_h, *mid_h;
    float* partial;
    cudaGetSymbolAddress((void**)&gwT_h,  g_gwT_h);
    cudaGetSymbolAddress((void**)&x_h,    g_x_h);
    cudaGetSymbolAddress((void**)&adj_h,  g_adj_h);
    cudaGetSymbolAddress((void**)&fcw_h,  g_fcw_h);
    cudaGetSymbolAddress((void**)&supT_h, g_supT_h);
    cudaGetSymbolAddress((void**)&mid_h,  g_mid_h);
    cudaGetSymbolAddress((void**)&partial, g_partial);

    cudaFuncSetAttribute(gemm1r, cudaFuncAttributeMaxDynamicSharedMemorySize, R1_SMEM);
    cudaFuncSetAttribute((const void*)gemm_s<2,2>,  cudaFuncAttributeMaxDynamicSharedMemorySize, SMEM3);
    cudaFuncSetAttribute((const void*)gemm_s<3,16>, cudaFuncAttributeMaxDynamicSharedMemorySize, SMEM3);

    int nsm = 148;
    cudaDeviceGetAttribute(&nsm, cudaDevAttrMultiProcessorCount, 0);
    const int pgrid = 2 * nsm;

    // 0) preps
    prep_wh<<<NFEAT, NFEAT>>>(gcn_w, gwT_h);
    {
        long n0 = (long)BATCH * NODES * NFEAT / 4;    // x
        long n1 = (long)BATCH * NODES * NODES / 4;    // adj
        long n2 = (long)NFEAT * KTOT / 4;             // fc_w
        conv3<<<2048, 256>>>(x, x_h, n0, adj, adj_h, n1, fc_w, fcw_h, n2);
    }

    // 1) supT[b][g][node] = sum_f gwT[g][f] * x_b[node][f]  (resident-gwT persistent)
    gemm1r<<<pgrid, NTHR, R1_SMEM>>>(gwT_h, x_h, supT_h, BATCH);

    // 2) mid[b][node][g] = sum_k adj_b[node][k]*supT_b[g][k] + gcn_b[g]  (persistent)
    gemm_s<2,2><<<pgrid, NTHR, SMEM3>>>(
        adj_h, supT_h, NODES, NODES, gcn_b, nullptr, mid_h, BATCH * 2);

    // 3) partial[s][m][n] = sum_{k in slice} mid[m][k]*fcw[n][k]  (single wave)
    {
        dim3 grid(SPLITS, BATCH / 128, 2);
        gemm_s<3,16><<<grid, NTHR, SMEM3>>>(
            mid_h, fcw_h, KTOT, KTOT, nullptr, partial, nullptr, 1);
    }
    // 4) reduce + bias + output sections
    finalize<<<SEC / 256, 256>>>(partial, fc_b, x, out);
}